// round 15
// baseline (speedup 1.0000x reference)
#include <cuda_runtime.h>
#include <cuda_fp16.h>
#include <cstdint>

#define N_ROWS  131072
#define C_DIM   256
#define K_CODES 1024
#define NZQ     33554432
#define HWSZ    4096
#define ROWS_CTA 64
#define GRID    (N_ROWS / ROWS_CTA)
#define RCAP    16384
#define MARGIN  1.2e-4f

#define ESCALE    4096.0f          // 2^12: lift emb fp16 out of subnormal range
#define EINVSCALE 0.000244140625f  // 2^-12 (exact)

__device__ __half g_es[K_CODES * C_DIM];   // h0(e * 2^12)
__device__ float  g_e2[K_CODES];
__device__ float  g_z2[N_ROWS];
__device__ float  g_partial[GRID];
__device__ float  g_loss2[N_ROWS];
__device__ int    g_cnt;
__device__ int    g_worklist[RCAP];

__device__ __forceinline__ uint32_t smem_u32(const void* p){
  uint32_t a;
  asm("{ .reg .u64 t; cvta.to.shared.u64 t, %1; cvt.u32.u64 %0, t; }" : "=r"(a) : "l"(p));
  return a;
}
__device__ __forceinline__ uint32_t swz(uint32_t off){ return off ^ ((off >> 3) & 0x70); }

#define CPASYNC16(dst, src) \
  asm volatile("cp.async.cg.shared.global [%0], [%1], 16;" :: "r"(dst), "l"(src))
#define CPCOMMIT() asm volatile("cp.async.commit_group;")

#define LDSM_X4(r0,r1,r2,r3,addr) \
  asm volatile("ldmatrix.sync.aligned.m8n8.x4.shared.b16 {%0,%1,%2,%3}, [%4];" \
    : "=r"(r0), "=r"(r1), "=r"(r2), "=r"(r3) : "r"(addr))

#define MMA16816(c0,c1,c2,c3,a0,a1,a2,a3,b0,b1) \
  asm volatile("mma.sync.aligned.m16n8k16.row.col.f32.f16.f16.f32 " \
    "{%0,%1,%2,%3}, {%4,%5,%6,%7}, {%8,%9}, {%0,%1,%2,%3};" \
    : "+f"(c0), "+f"(c1), "+f"(c2), "+f"(c3) \
    : "r"(a0), "r"(a1), "r"(a2), "r"(a3), "r"(b0), "r"(b1))

#define STS128(addr, a0, a1, a2, a3) \
  asm volatile("st.shared.v4.b32 [%0], {%1,%2,%3,%4};" :: "r"(addr), "r"(a0), "r"(a1), "r"(a2), "r"(a3) : "memory")

// ---------------- prep: emb h0 (scaled) + exact ||e||^2 ----------------
__global__ void prep_e(const float* __restrict__ emb){
  int k = blockIdx.x, c = threadIdx.x;
  float v = emb[k * C_DIM + c];
  g_es[k * C_DIM + c] = __float2half_rn(v * ESCALE);
  __shared__ float red[C_DIM];
  red[c] = __fmul_rn(v, v);
  __syncthreads();
  for (int s = 128; s > 0; s >>= 1){
    if (c < s) red[c] = __fadd_rn(red[c], red[c + s]);
    __syncthreads();
  }
  if (c == 0) g_e2[k] = red[0];
}

__global__ void zero_cnt(){ g_cnt = 0; }
__global__ void dummy_k(){}

// ---------------- filter: 1-pass fp16 GEMM + top-2 + fused epilogue ----------------
// smem: A[4kc][64r][64c]h0 = 32K | B[2buf][128code][64c] = 32K | e2s 4K |
//       z2s 256 | V1 1K | I1 1K | V2 1K | sidx 256 | amb 256 | red 1K
#define SM_A      0
#define SM_B      32768
#define OFF_E2S   65536
#define OFF_Z2S   69632
#define OFF_V1    69888
#define OFF_I1    70912
#define OFF_V2    71936
#define OFF_SIDX  72960
#define OFF_AMB   73216
#define OFF_RED   73472
#define SM_TOTAL  74496

__global__ __launch_bounds__(256, 2) void vq_filt(const float* __restrict__ z,
                                                  const float* __restrict__ emb,
                                                  float* __restrict__ out,
                                                  int out_size){
  extern __shared__ char smem[];
  const uint32_t sb = smem_u32(smem);
  float* e2s  = (float*)(smem + OFF_E2S);
  float* z2s  = (float*)(smem + OFF_Z2S);
  float* V1   = (float*)(smem + OFF_V1);
  int*   I1   = (int*)(smem + OFF_I1);
  float* V2   = (float*)(smem + OFF_V2);
  int*   sidx = (int*)(smem + OFF_SIDX);
  int*   samb = (int*)(smem + OFF_AMB);
  float* red  = (float*)(smem + OFF_RED);

  const int t = threadIdx.x, w = t >> 5, l = t & 31;
  const int wm = (w & 1) * 32;        // 2 m-warps x 32 rows
  const int g  = w >> 1;              // 4 n-warp groups
  const int wn = g * 32;              // 32 codes per warp within 128-code tile
  const int n0 = blockIdx.x * ROWS_CTA;
  const int b  = n0 >> 12, hw0 = n0 & 4095;
  const float* zb = z + (size_t)b * (C_DIM * HWSZ) + hw0;

  // B stage: [128 code][64 c] h0 = 16KB
  auto issue = [&](int stage){
    const int nt2 = stage >> 2, kc2 = stage & 3, buf2 = stage & 1;
    #pragma unroll
    for (int i = 0; i < 4; ++i){
      int id = t + i * 256;           // 0..1023 x 16B
      int r = id >> 3, j = id & 7;
      const __half* src = g_es + (size_t)(nt2 * 128 + r) * C_DIM + kc2 * 64 + j * 8;
      CPASYNC16(sb + SM_B + buf2 * 16384 + swz((uint32_t)(r * 128 + j * 16)), src);
    }
    CPCOMMIT();
  };

  issue(0);
  issue(1);

  // ---- phase 1: h0-split z -> A smem (4 thr/row); t<64 z2 sequential ----
  {
    const int row = t & 63, q = t >> 6;   // q = kc block (64 dims)
    #pragma unroll
    for (int cg = 0; cg < 8; ++cg){
      uint32_t p0[4];
      #pragma unroll
      for (int j2 = 0; j2 < 4; ++j2){
        int c = q * 64 + cg * 8 + j2 * 2;
        uint32_t a0 = (uint32_t)__half_as_ushort(__float2half_rn(__ldg(zb + (size_t)c * HWSZ + row)));
        uint32_t b0 = (uint32_t)__half_as_ushort(__float2half_rn(__ldg(zb + (size_t)(c + 1) * HWSZ + row)));
        p0[j2] = a0 | (b0 << 16);
      }
      STS128(sb + SM_A + q * 8192 + swz((uint32_t)(row * 128 + cg * 16)),
             p0[0], p0[1], p0[2], p0[3]);
    }
  }
  for (int i = t; i < 1024; i += 256) e2s[i] = g_e2[i];
  if (t < 64){
    float acc2 = 0.f;
    #pragma unroll 8
    for (int c = 0; c < 256; ++c){
      float v = __ldg(zb + (size_t)c * HWSZ + t);
      acc2 = __fadd_rn(acc2, __fmul_rn(v, v));
    }
    z2s[t] = acc2;
    g_z2[n0 + t] = acc2;
  }
  __syncthreads();

  float acc[2][4][4];
  float rv1[4], rv2[4]; int ri1[4];
  #pragma unroll
  for (int s2 = 0; s2 < 4; ++s2){ rv1[s2] = 3.4028235e38f; rv2[s2] = 3.4028235e38f; ri1[s2] = 0; }

  const uint32_t arow = (uint32_t)(wm + (l & 7) + ((l >> 3) & 1) * 8);
  const uint32_t nrow0 = (uint32_t)(wn + ((l >> 4) << 3) + (l & 7));
  const uint32_t nrow1 = nrow0 + 16;

  for (int st = 0; st < 32; ++st){
    const int nt = st >> 2, kc = st & 3, buf = st & 1;

    if (st < 31) asm volatile("cp.async.wait_group 1;" ::: "memory");
    else         asm volatile("cp.async.wait_group 0;" ::: "memory");
    __syncthreads();

    if (kc == 0){
      #pragma unroll
      for (int ma = 0; ma < 2; ++ma)
        #pragma unroll
        for (int na = 0; na < 4; ++na)
          #pragma unroll
          for (int q = 0; q < 4; ++q) acc[ma][na][q] = 0.f;
    }

    const uint32_t Ab = sb + SM_A + (uint32_t)kc * 8192;
    const uint32_t Bb = sb + SM_B + (uint32_t)buf * 16384;

    #pragma unroll
    for (int k16 = 0; k16 < 4; ++k16){
      const uint32_t kbA = (uint32_t)(k16 * 32) + (uint32_t)((l >> 4) << 4);
      const uint32_t kbB = (uint32_t)(k16 * 32) + (uint32_t)(((l >> 3) & 1) << 4);
      uint32_t af[2][4], bf[4][2];
      #pragma unroll
      for (int ma = 0; ma < 2; ++ma)
        LDSM_X4(af[ma][0], af[ma][1], af[ma][2], af[ma][3],
                Ab + swz((arow + ma * 16) * 128 + kbA));
      LDSM_X4(bf[0][0], bf[0][1], bf[1][0], bf[1][1], Bb + swz(nrow0 * 128 + kbB));
      LDSM_X4(bf[2][0], bf[2][1], bf[3][0], bf[3][1], Bb + swz(nrow1 * 128 + kbB));
      #pragma unroll
      for (int ma = 0; ma < 2; ++ma)
        #pragma unroll
        for (int na = 0; na < 4; ++na)
          MMA16816(acc[ma][na][0], acc[ma][na][1], acc[ma][na][2], acc[ma][na][3],
                   af[ma][0], af[ma][1], af[ma][2], af[ma][3], bf[na][0], bf[na][1]);
    }
    __syncthreads();
    if (st + 2 < 32) issue(st + 2);

    // ---- per-nt top-2 update ----
    if (kc == 3){
      #pragma unroll
      for (int ma = 0; ma < 2; ++ma){
        #pragma unroll
        for (int h = 0; h < 2; ++h){
          int slot = ma * 2 + h;
          int row = wm + ma * 16 + (l >> 2) + h * 8;
          float z2v = z2s[row];
          #pragma unroll
          for (int na = 0; na < 4; ++na){
            #pragma unroll
            for (int c2 = 0; c2 < 2; ++c2){
              int code = nt * 128 + wn + na * 8 + (l & 3) * 2 + c2;
              float dot = acc[ma][na][h * 2 + c2] * EINVSCALE;
              float dist = __fsub_rn(__fadd_rn(z2v, e2s[code]), __fmul_rn(2.0f, dot));
              if (dist < rv1[slot]){ rv2[slot] = rv1[slot]; rv1[slot] = dist; ri1[slot] = code; }
              else if (dist < rv2[slot]){ rv2[slot] = dist; }
            }
          }
        }
      }
    }
  }

  // ---- lane top-2 merge (xor 1,2 over the 4 lanes per row) ----
  #pragma unroll
  for (int slot = 0; slot < 4; ++slot){
    #pragma unroll
    for (int m = 1; m <= 2; m <<= 1){
      float o1 = __shfl_xor_sync(0xffffffffu, rv1[slot], m);
      int   oi = __shfl_xor_sync(0xffffffffu, ri1[slot], m);
      float o2 = __shfl_xor_sync(0xffffffffu, rv2[slot], m);
      if (o1 < rv1[slot] || (o1 == rv1[slot] && oi < ri1[slot])){
        rv2[slot] = fminf(rv1[slot], o2); rv1[slot] = o1; ri1[slot] = oi;
      } else {
        rv2[slot] = fminf(rv2[slot], o1);
      }
    }
  }
  if ((l & 3) == 0){
    #pragma unroll
    for (int slot = 0; slot < 4; ++slot){
      int row = wm + (slot >> 1) * 16 + (l >> 2) + (slot & 1) * 8;
      V1[g * 64 + row] = rv1[slot]; I1[g * 64 + row] = ri1[slot]; V2[g * 64 + row] = rv2[slot];
    }
  }
  __syncthreads();

  // ---- cross-group merge + ambiguity decision ----
  if (t < 64){
    float v1 = V1[t]; int i1 = I1[t]; float v2 = V2[t];
    #pragma unroll
    for (int gg = 1; gg < 4; ++gg){
      float o1 = V1[gg * 64 + t]; int oi = I1[gg * 64 + t]; float o2 = V2[gg * 64 + t];
      if (o1 < v1 || (o1 == v1 && oi < i1)){ v2 = fminf(v1, o2); v1 = o1; i1 = oi; }
      else v2 = fminf(v2, o1);
    }
    int n = n0 + t;
    bool amb = (__fsub_rn(v2, v1) <= MARGIN);
    if (amb){
      int pos = atomicAdd(&g_cnt, 1);
      if (pos < RCAP){
        g_worklist[pos] = n;
        samb[t] = 1;
        sidx[t] = i1;          // unused placeholder
      } else {
        amb = false;           // overflow fallback: best-effort
      }
    }
    if (!amb){
      samb[t] = 0;
      sidx[t] = i1;
      g_loss2[n] = 0.f;
      if (out_size >= NZQ + N_ROWS) out[NZQ + n] = (float)i1;
    }
  }
  __syncthreads();

  // ---- fused epilogue for unambiguous rows ----
  {
    const int i = t & 63, q = t >> 6;
    const int code = sidx[i];
    const int skip = samb[i];
    const float* erow = emb + (size_t)code * C_DIM;
    float lacc = 0.f;
    const bool wr = (out_size >= NZQ);
    if (!skip){
      #pragma unroll 4
      for (int c = q; c < 256; c += 4){
        float e  = __ldg(&erow[c]);
        size_t a = (size_t)b * (C_DIM * HWSZ) + hw0 + (size_t)c * HWSZ + i;
        float zp = z[a];
        float d  = __fsub_rn(e, zp);
        if (wr) out[a] = __fadd_rn(zp, d);
        lacc = __fadd_rn(lacc, __fmul_rn(d, d));
      }
    }
    red[t] = lacc;
    __syncthreads();
    for (int s = 128; s > 0; s >>= 1){
      if (t < s) red[t] = __fadd_rn(red[t], red[t + s]);
      __syncthreads();
    }
    if (t == 0) g_partial[blockIdx.x] = red[0];
  }
}

// ---------------- refine: exact fp32 argmin for ambiguous rows ----------------
__global__ __launch_bounds__(256) void vq_refine(const float* __restrict__ z,
                                                 const float* __restrict__ emb,
                                                 float* __restrict__ out,
                                                 int out_size){
  int cnt = g_cnt; if (cnt > RCAP) cnt = RCAP;
  if ((int)blockIdx.x >= cnt) return;
  const int n = g_worklist[blockIdx.x];
  const int b = n >> 12, hw = n & 4095;
  const int t = threadIdx.x;
  __shared__ float zrow[256];
  __shared__ float rv[256];
  __shared__ int   ri[256];

  zrow[t] = z[(size_t)(b * 256 + t) * HWSZ + hw];
  __syncthreads();
  const float z2 = g_z2[n];

  // 4 codes per thread, interleaved chains (each chain ascending-c sequential)
  const int c0 = t * 4;
  const float4* er0 = (const float4*)(emb + (size_t)(c0 + 0) * C_DIM);
  const float4* er1 = (const float4*)(emb + (size_t)(c0 + 1) * C_DIM);
  const float4* er2 = (const float4*)(emb + (size_t)(c0 + 2) * C_DIM);
  const float4* er3 = (const float4*)(emb + (size_t)(c0 + 3) * C_DIM);
  float d0 = 0.f, d1 = 0.f, d2 = 0.f, d3 = 0.f;
  #pragma unroll 4
  for (int c4 = 0; c4 < 64; ++c4){
    float zx = zrow[c4 * 4 + 0], zy = zrow[c4 * 4 + 1], zz = zrow[c4 * 4 + 2], zw = zrow[c4 * 4 + 3];
    float4 v0 = __ldg(er0 + c4), v1 = __ldg(er1 + c4), v2 = __ldg(er2 + c4), v3 = __ldg(er3 + c4);
    d0 = __fmaf_rn(zx, v0.x, d0); d0 = __fmaf_rn(zy, v0.y, d0); d0 = __fmaf_rn(zz, v0.z, d0); d0 = __fmaf_rn(zw, v0.w, d0);
    d1 = __fmaf_rn(zx, v1.x, d1); d1 = __fmaf_rn(zy, v1.y, d1); d1 = __fmaf_rn(zz, v1.z, d1); d1 = __fmaf_rn(zw, v1.w, d1);
    d2 = __fmaf_rn(zx, v2.x, d2); d2 = __fmaf_rn(zy, v2.y, d2); d2 = __fmaf_rn(zz, v2.z, d2); d2 = __fmaf_rn(zw, v2.w, d2);
    d3 = __fmaf_rn(zx, v3.x, d3); d3 = __fmaf_rn(zy, v3.y, d3); d3 = __fmaf_rn(zz, v3.z, d3); d3 = __fmaf_rn(zw, v3.w, d3);
  }
  float bv = 3.4028235e38f; int bi = 0;
  float dd[4] = {d0, d1, d2, d3};
  #pragma unroll
  for (int j = 0; j < 4; ++j){
    float dist = __fsub_rn(__fadd_rn(z2, __ldg(&g_e2[c0 + j])), __fmul_rn(2.0f, dd[j]));
    if (dist < bv){ bv = dist; bi = c0 + j; }
  }
  rv[t] = bv; ri[t] = bi;
  __syncthreads();
  for (int s = 128; s > 0; s >>= 1){
    if (t < s){
      float ov = rv[t + s]; int oi = ri[t + s];
      if (ov < rv[t] || (ov == rv[t] && oi < ri[t])){ rv[t] = ov; ri[t] = oi; }
    }
    __syncthreads();
  }
  const int idx = ri[0];
  if (t == 0 && out_size >= NZQ + N_ROWS) out[NZQ + n] = (float)idx;
  __syncthreads();

  // epilogue: one column per thread
  float e  = __ldg(emb + (size_t)idx * C_DIM + t);
  float zp = zrow[t];
  float d  = __fsub_rn(e, zp);
  if (out_size >= NZQ) out[(size_t)(b * 256 + t) * HWSZ + hw] = __fadd_rn(zp, d);
  rv[t] = __fmul_rn(d, d);
  __syncthreads();
  for (int s = 128; s > 0; s >>= 1){
    if (t < s) rv[t] = __fadd_rn(rv[t], rv[t + s]);
    __syncthreads();
  }
  if (t == 0) g_loss2[n] = rv[0];
}

// ---------------- final loss ----------------
__global__ void vq_fin(float* __restrict__ out, int out_size){
  __shared__ double dred[256];
  const int t = threadIdx.x;
  double s = 0.0;
  for (int ii = t; ii < GRID; ii += 256) s += (double)g_partial[ii];
  for (int ii = t; ii < N_ROWS; ii += 256) s += (double)g_loss2[ii];
  dred[t] = s;
  __syncthreads();
  for (int k = 128; k > 0; k >>= 1){
    if (t < k) dred[t] += dred[t + k];
    __syncthreads();
  }
  if (t == 0 && out_size >= NZQ + N_ROWS + 1){
    float m1 = (float)(dred[0] / 33554432.0);
    float loss = __fsub_rn(m1, __fmul_rn(0.25f, m1));
    out[NZQ + N_ROWS] = loss;
  }
}

extern "C" void kernel_launch(void* const* d_in, const int* in_sizes, int n_in,
                              void* d_out, int out_size){
  const float* z   = (const float*)d_in[0];
  const float* emb = (const float*)d_in[1];
  float* out = (float*)d_out;
  (void)in_sizes; (void)n_in;

  cudaFuncSetAttribute(vq_filt, cudaFuncAttributeMaxDynamicSharedMemorySize, SM_TOTAL);

  zero_cnt<<<1, 1>>>();                      // launch 0
  prep_e<<<K_CODES, C_DIM>>>(emb);           // launch 1
  dummy_k<<<1, 32>>>();                      // launch 2
  vq_filt<<<GRID, 256, SM_TOTAL>>>(z, emb, out, out_size);  // launch 3 (ncu target)
  vq_refine<<<RCAP, 256>>>(z, emb, out, out_size);          // launch 4
  vq_fin<<<1, 256>>>(out, out_size);         // launch 5
}

// round 16
// speedup vs baseline: 1.4370x; 1.4370x over previous
#include <cuda_runtime.h>
#include <cuda_fp16.h>
#include <cstdint>

#define N_ROWS  131072
#define C_DIM   256
#define K_CODES 1024
#define NZQ     33554432
#define HWSZ    4096
#define ROWS_CTA 64
#define GRID    (N_ROWS / ROWS_CTA)
#define RCAP    16384
#define MARGIN  1.2e-4f
#define RB_ROWS 32

#define ESCALE    4096.0f          // 2^12: lift emb fp16 out of subnormal range
#define EINVSCALE 0.000244140625f  // 2^-12 (exact)

__device__ __half g_es[K_CODES * C_DIM];   // h0(e * 2^12)
__device__ float  g_e2[K_CODES];
__device__ float  g_z2[N_ROWS];
__device__ float  g_partial[GRID];
__device__ float  g_loss2[N_ROWS];
__device__ int    g_cnt;
__device__ int    g_worklist[RCAP];

__device__ __forceinline__ uint32_t smem_u32(const void* p){
  uint32_t a;
  asm("{ .reg .u64 t; cvta.to.shared.u64 t, %1; cvt.u32.u64 %0, t; }" : "=r"(a) : "l"(p));
  return a;
}
__device__ __forceinline__ uint32_t swz(uint32_t off){ return off ^ ((off >> 3) & 0x70); }

#define CPASYNC16(dst, src) \
  asm volatile("cp.async.cg.shared.global [%0], [%1], 16;" :: "r"(dst), "l"(src))
#define CPCOMMIT() asm volatile("cp.async.commit_group;")

#define LDSM_X4(r0,r1,r2,r3,addr) \
  asm volatile("ldmatrix.sync.aligned.m8n8.x4.shared.b16 {%0,%1,%2,%3}, [%4];" \
    : "=r"(r0), "=r"(r1), "=r"(r2), "=r"(r3) : "r"(addr))

#define MMA16816(c0,c1,c2,c3,a0,a1,a2,a3,b0,b1) \
  asm volatile("mma.sync.aligned.m16n8k16.row.col.f32.f16.f16.f32 " \
    "{%0,%1,%2,%3}, {%4,%5,%6,%7}, {%8,%9}, {%0,%1,%2,%3};" \
    : "+f"(c0), "+f"(c1), "+f"(c2), "+f"(c3) \
    : "r"(a0), "r"(a1), "r"(a2), "r"(a3), "r"(b0), "r"(b1))

#define STS128(addr, a0, a1, a2, a3) \
  asm volatile("st.shared.v4.b32 [%0], {%1,%2,%3,%4};" :: "r"(addr), "r"(a0), "r"(a1), "r"(a2), "r"(a3) : "memory")

// ---------------- prep: emb h0 (scaled) + exact ||e||^2 ----------------
__global__ void prep_e(const float* __restrict__ emb){
  int k = blockIdx.x, c = threadIdx.x;
  float v = emb[k * C_DIM + c];
  g_es[k * C_DIM + c] = __float2half_rn(v * ESCALE);
  __shared__ float red[C_DIM];
  red[c] = __fmul_rn(v, v);
  __syncthreads();
  for (int s = 128; s > 0; s >>= 1){
    if (c < s) red[c] = __fadd_rn(red[c], red[c + s]);
    __syncthreads();
  }
  if (c == 0) g_e2[k] = red[0];
}

__global__ void zero_cnt(){ g_cnt = 0; }
__global__ void dummy_k(){}

// ---------------- filter: 1-pass fp16 GEMM + top-2 + fused epilogue (R15, unchanged) ----------------
#define SM_A      0
#define SM_B      32768
#define OFF_E2S   65536
#define OFF_Z2S   69632
#define OFF_V1    69888
#define OFF_I1    70912
#define OFF_V2    71936
#define OFF_SIDX  72960
#define OFF_AMB   73216
#define OFF_RED   73472
#define SM_TOTAL  74496

__global__ __launch_bounds__(256, 2) void vq_filt(const float* __restrict__ z,
                                                  const float* __restrict__ emb,
                                                  float* __restrict__ out,
                                                  int out_size){
  extern __shared__ char smem[];
  const uint32_t sb = smem_u32(smem);
  float* e2s  = (float*)(smem + OFF_E2S);
  float* z2s  = (float*)(smem + OFF_Z2S);
  float* V1   = (float*)(smem + OFF_V1);
  int*   I1   = (int*)(smem + OFF_I1);
  float* V2   = (float*)(smem + OFF_V2);
  int*   sidx = (int*)(smem + OFF_SIDX);
  int*   samb = (int*)(smem + OFF_AMB);
  float* red  = (float*)(smem + OFF_RED);

  const int t = threadIdx.x, w = t >> 5, l = t & 31;
  const int wm = (w & 1) * 32;
  const int g  = w >> 1;
  const int wn = g * 32;
  const int n0 = blockIdx.x * ROWS_CTA;
  const int b  = n0 >> 12, hw0 = n0 & 4095;
  const float* zb = z + (size_t)b * (C_DIM * HWSZ) + hw0;

  auto issue = [&](int stage){
    const int nt2 = stage >> 2, kc2 = stage & 3, buf2 = stage & 1;
    #pragma unroll
    for (int i = 0; i < 4; ++i){
      int id = t + i * 256;
      int r = id >> 3, j = id & 7;
      const __half* src = g_es + (size_t)(nt2 * 128 + r) * C_DIM + kc2 * 64 + j * 8;
      CPASYNC16(sb + SM_B + buf2 * 16384 + swz((uint32_t)(r * 128 + j * 16)), src);
    }
    CPCOMMIT();
  };

  issue(0);
  issue(1);

  {
    const int row = t & 63, q = t >> 6;
    #pragma unroll
    for (int cg = 0; cg < 8; ++cg){
      uint32_t p0[4];
      #pragma unroll
      for (int j2 = 0; j2 < 4; ++j2){
        int c = q * 64 + cg * 8 + j2 * 2;
        uint32_t a0 = (uint32_t)__half_as_ushort(__float2half_rn(__ldg(zb + (size_t)c * HWSZ + row)));
        uint32_t b0 = (uint32_t)__half_as_ushort(__float2half_rn(__ldg(zb + (size_t)(c + 1) * HWSZ + row)));
        p0[j2] = a0 | (b0 << 16);
      }
      STS128(sb + SM_A + q * 8192 + swz((uint32_t)(row * 128 + cg * 16)),
             p0[0], p0[1], p0[2], p0[3]);
    }
  }
  for (int i = t; i < 1024; i += 256) e2s[i] = g_e2[i];
  if (t < 64){
    float acc2 = 0.f;
    #pragma unroll 8
    for (int c = 0; c < 256; ++c){
      float v = __ldg(zb + (size_t)c * HWSZ + t);
      acc2 = __fadd_rn(acc2, __fmul_rn(v, v));
    }
    z2s[t] = acc2;
    g_z2[n0 + t] = acc2;
  }
  __syncthreads();

  float acc[2][4][4];
  float rv1[4], rv2[4]; int ri1[4];
  #pragma unroll
  for (int s2 = 0; s2 < 4; ++s2){ rv1[s2] = 3.4028235e38f; rv2[s2] = 3.4028235e38f; ri1[s2] = 0; }

  const uint32_t arow = (uint32_t)(wm + (l & 7) + ((l >> 3) & 1) * 8);
  const uint32_t nrow0 = (uint32_t)(wn + ((l >> 4) << 3) + (l & 7));
  const uint32_t nrow1 = nrow0 + 16;

  for (int st = 0; st < 32; ++st){
    const int nt = st >> 2, kc = st & 3, buf = st & 1;

    if (st < 31) asm volatile("cp.async.wait_group 1;" ::: "memory");
    else         asm volatile("cp.async.wait_group 0;" ::: "memory");
    __syncthreads();

    if (kc == 0){
      #pragma unroll
      for (int ma = 0; ma < 2; ++ma)
        #pragma unroll
        for (int na = 0; na < 4; ++na)
          #pragma unroll
          for (int q = 0; q < 4; ++q) acc[ma][na][q] = 0.f;
    }

    const uint32_t Ab = sb + SM_A + (uint32_t)kc * 8192;
    const uint32_t Bb = sb + SM_B + (uint32_t)buf * 16384;

    #pragma unroll
    for (int k16 = 0; k16 < 4; ++k16){
      const uint32_t kbA = (uint32_t)(k16 * 32) + (uint32_t)((l >> 4) << 4);
      const uint32_t kbB = (uint32_t)(k16 * 32) + (uint32_t)(((l >> 3) & 1) << 4);
      uint32_t af[2][4], bf[4][2];
      #pragma unroll
      for (int ma = 0; ma < 2; ++ma)
        LDSM_X4(af[ma][0], af[ma][1], af[ma][2], af[ma][3],
                Ab + swz((arow + ma * 16) * 128 + kbA));
      LDSM_X4(bf[0][0], bf[0][1], bf[1][0], bf[1][1], Bb + swz(nrow0 * 128 + kbB));
      LDSM_X4(bf[2][0], bf[2][1], bf[3][0], bf[3][1], Bb + swz(nrow1 * 128 + kbB));
      #pragma unroll
      for (int ma = 0; ma < 2; ++ma)
        #pragma unroll
        for (int na = 0; na < 4; ++na)
          MMA16816(acc[ma][na][0], acc[ma][na][1], acc[ma][na][2], acc[ma][na][3],
                   af[ma][0], af[ma][1], af[ma][2], af[ma][3], bf[na][0], bf[na][1]);
    }
    __syncthreads();
    if (st + 2 < 32) issue(st + 2);

    if (kc == 3){
      #pragma unroll
      for (int ma = 0; ma < 2; ++ma){
        #pragma unroll
        for (int h = 0; h < 2; ++h){
          int slot = ma * 2 + h;
          int row = wm + ma * 16 + (l >> 2) + h * 8;
          float z2v = z2s[row];
          #pragma unroll
          for (int na = 0; na < 4; ++na){
            #pragma unroll
            for (int c2 = 0; c2 < 2; ++c2){
              int code = nt * 128 + wn + na * 8 + (l & 3) * 2 + c2;
              float dot = acc[ma][na][h * 2 + c2] * EINVSCALE;
              float dist = __fsub_rn(__fadd_rn(z2v, e2s[code]), __fmul_rn(2.0f, dot));
              if (dist < rv1[slot]){ rv2[slot] = rv1[slot]; rv1[slot] = dist; ri1[slot] = code; }
              else if (dist < rv2[slot]){ rv2[slot] = dist; }
            }
          }
        }
      }
    }
  }

  #pragma unroll
  for (int slot = 0; slot < 4; ++slot){
    #pragma unroll
    for (int m = 1; m <= 2; m <<= 1){
      float o1 = __shfl_xor_sync(0xffffffffu, rv1[slot], m);
      int   oi = __shfl_xor_sync(0xffffffffu, ri1[slot], m);
      float o2 = __shfl_xor_sync(0xffffffffu, rv2[slot], m);
      if (o1 < rv1[slot] || (o1 == rv1[slot] && oi < ri1[slot])){
        rv2[slot] = fminf(rv1[slot], o2); rv1[slot] = o1; ri1[slot] = oi;
      } else {
        rv2[slot] = fminf(rv2[slot], o1);
      }
    }
  }
  if ((l & 3) == 0){
    #pragma unroll
    for (int slot = 0; slot < 4; ++slot){
      int row = wm + (slot >> 1) * 16 + (l >> 2) + (slot & 1) * 8;
      V1[g * 64 + row] = rv1[slot]; I1[g * 64 + row] = ri1[slot]; V2[g * 64 + row] = rv2[slot];
    }
  }
  __syncthreads();

  if (t < 64){
    float v1 = V1[t]; int i1 = I1[t]; float v2 = V2[t];
    #pragma unroll
    for (int gg = 1; gg < 4; ++gg){
      float o1 = V1[gg * 64 + t]; int oi = I1[gg * 64 + t]; float o2 = V2[gg * 64 + t];
      if (o1 < v1 || (o1 == v1 && oi < i1)){ v2 = fminf(v1, o2); v1 = o1; i1 = oi; }
      else v2 = fminf(v2, o1);
    }
    int n = n0 + t;
    bool amb = (__fsub_rn(v2, v1) <= MARGIN);
    if (amb){
      int pos = atomicAdd(&g_cnt, 1);
      if (pos < RCAP){
        g_worklist[pos] = n;
        samb[t] = 1;
        sidx[t] = i1;
      } else {
        amb = false;
      }
    }
    if (!amb){
      samb[t] = 0;
      sidx[t] = i1;
      g_loss2[n] = 0.f;
      if (out_size >= NZQ + N_ROWS) out[NZQ + n] = (float)i1;
    }
  }
  __syncthreads();

  {
    const int i = t & 63, q = t >> 6;
    const int code = sidx[i];
    const int skip = samb[i];
    const float* erow = emb + (size_t)code * C_DIM;
    float lacc = 0.f;
    const bool wr = (out_size >= NZQ);
    if (!skip){
      #pragma unroll 4
      for (int c = q; c < 256; c += 4){
        float e  = __ldg(&erow[c]);
        size_t a = (size_t)b * (C_DIM * HWSZ) + hw0 + (size_t)c * HWSZ + i;
        float zp = z[a];
        float d  = __fsub_rn(e, zp);
        if (wr) out[a] = __fadd_rn(zp, d);
        lacc = __fadd_rn(lacc, __fmul_rn(d, d));
      }
    }
    red[t] = lacc;
    __syncthreads();
    for (int s = 128; s > 0; s >>= 1){
      if (t < s) red[t] = __fadd_rn(red[t], red[t + s]);
      __syncthreads();
    }
    if (t == 0) g_partial[blockIdx.x] = red[0];
  }
}

// ---------------- refine: batched exact fp32 argmin (32 rows/block) ----------------
// smem: zs[256 c][32 r] 32K | es[32 k][128 code] 16K | rv[32][33] | ri[32][33] | meta
#define R_SM_ZS    0
#define R_SM_ES    32768
#define R_SM_RV    49152
#define R_SM_RI    53504
#define R_SM_META  57856
#define R_SM_TOTAL 58496

__global__ __launch_bounds__(256) void vq_refine(const float* __restrict__ z,
                                                 const float* __restrict__ emb,
                                                 float* __restrict__ out,
                                                 int out_size){
  extern __shared__ char rsm[];
  float* zs  = (float*)(rsm + R_SM_ZS);     // [c][32]
  float* es  = (float*)(rsm + R_SM_ES);     // [k][128]
  float* rv  = (float*)(rsm + R_SM_RV);     // [32][33]
  int*   ri  = (int*)(rsm + R_SM_RI);       // [32][33]
  int*   mn  = (int*)(rsm + R_SM_META);
  int*   mb  = mn + 32;
  int*   mhw = mb + 32;
  float* mz2 = (float*)(mhw + 32);
  int*   midx = (int*)(mz2 + 32);

  int cnt = g_cnt; if (cnt > RCAP) cnt = RCAP;
  const int base = blockIdx.x * RB_ROWS;
  if (base >= cnt) return;
  const int nvalid = min(RB_ROWS, cnt - base);
  const int t = threadIdx.x;

  if (t < 32){
    int n = g_worklist[base + ((t < nvalid) ? t : 0)];
    mn[t] = n; mb[t] = n >> 12; mhw[t] = n & 4095;
    mz2[t] = g_z2[n];
  }
  __syncthreads();

  // load 32 z rows transposed into zs[c][r]
  #pragma unroll 4
  for (int i = 0; i < 32; ++i){
    int id = t + i * 256;
    int r = id & 31, c = id >> 5;
    zs[c * 32 + r] = __ldg(z + (size_t)(mb[r] * 256 + c) * HWSZ + mhw[r]);
  }

  const int tr = t & 7, tc = t >> 3;   // 8 row-groups x 32 code-groups
  float bestv[4]; int besti[4];
  #pragma unroll
  for (int i = 0; i < 4; ++i){ bestv[i] = 3.4028235e38f; besti[i] = 0; }

  for (int ct = 0; ct < 8; ++ct){
    float acc[4][4];
    #pragma unroll
    for (int i = 0; i < 4; ++i)
      #pragma unroll
      for (int j = 0; j < 4; ++j) acc[i][j] = 0.f;

    for (int kc = 0; kc < 8; ++kc){
      __syncthreads();
      #pragma unroll
      for (int i = 0; i < 16; ++i){
        int id = t + i * 256;
        int k = id & 31, code = id >> 5;
        es[k * 128 + code] = __ldg(emb + (size_t)(ct * 128 + code) * C_DIM + kc * 32 + k);
      }
      __syncthreads();
      #pragma unroll 8
      for (int k = 0; k < 32; ++k){
        float4 zv = *(const float4*)&zs[(kc * 32 + k) * 32 + tr * 4];
        float4 ev = *(const float4*)&es[k * 128 + tc * 4];
        acc[0][0] = __fmaf_rn(zv.x, ev.x, acc[0][0]);
        acc[0][1] = __fmaf_rn(zv.x, ev.y, acc[0][1]);
        acc[0][2] = __fmaf_rn(zv.x, ev.z, acc[0][2]);
        acc[0][3] = __fmaf_rn(zv.x, ev.w, acc[0][3]);
        acc[1][0] = __fmaf_rn(zv.y, ev.x, acc[1][0]);
        acc[1][1] = __fmaf_rn(zv.y, ev.y, acc[1][1]);
        acc[1][2] = __fmaf_rn(zv.y, ev.z, acc[1][2]);
        acc[1][3] = __fmaf_rn(zv.y, ev.w, acc[1][3]);
        acc[2][0] = __fmaf_rn(zv.z, ev.x, acc[2][0]);
        acc[2][1] = __fmaf_rn(zv.z, ev.y, acc[2][1]);
        acc[2][2] = __fmaf_rn(zv.z, ev.z, acc[2][2]);
        acc[2][3] = __fmaf_rn(zv.z, ev.w, acc[2][3]);
        acc[3][0] = __fmaf_rn(zv.w, ev.x, acc[3][0]);
        acc[3][1] = __fmaf_rn(zv.w, ev.y, acc[3][1]);
        acc[3][2] = __fmaf_rn(zv.w, ev.z, acc[3][2]);
        acc[3][3] = __fmaf_rn(zv.w, ev.w, acc[3][3]);
      }
    }
    // distances + best update (codes ascend: ct outer, j inner)
    #pragma unroll
    for (int j = 0; j < 4; ++j){
      int code = ct * 128 + tc * 4 + j;
      float e2v = __ldg(&g_e2[code]);
      #pragma unroll
      for (int i = 0; i < 4; ++i){
        float dist = __fsub_rn(__fadd_rn(mz2[tr * 4 + i], e2v), __fmul_rn(2.0f, acc[i][j]));
        if (dist < bestv[i]){ bestv[i] = dist; besti[i] = code; }
      }
    }
  }

  #pragma unroll
  for (int i = 0; i < 4; ++i){
    rv[(tr * 4 + i) * 33 + tc] = bestv[i];
    ri[(tr * 4 + i) * 33 + tc] = besti[i];
  }
  __syncthreads();
  if (t < 32){
    if (t < nvalid){
      float bv = rv[t * 33]; int bi = ri[t * 33];
      #pragma unroll 4
      for (int q = 1; q < 32; ++q){
        float ov = rv[t * 33 + q]; int oi = ri[t * 33 + q];
        if (ov < bv || (ov == bv && oi < bi)){ bv = ov; bi = oi; }
      }
      midx[t] = bi;
      if (out_size >= NZQ + N_ROWS) out[NZQ + mn[t]] = (float)bi;
    }
  }
  __syncthreads();

  // epilogue: r = t&31 owns row, cg = t>>5 covers 32 dims
  {
    const int r = t & 31, cg = t >> 5;
    float lacc = 0.f;
    if (r < nvalid){
      const int code = midx[r];
      const bool wr = (out_size >= NZQ);
      const size_t basea = (size_t)(mb[r] * 256) * HWSZ + mhw[r];
      #pragma unroll 4
      for (int j = 0; j < 32; ++j){
        int c = cg * 32 + j;
        float e  = __ldg(emb + (size_t)code * C_DIM + c);
        float zp = zs[c * 32 + r];
        float d  = __fsub_rn(e, zp);
        if (wr) out[basea + (size_t)c * HWSZ] = __fadd_rn(zp, d);
        lacc = __fadd_rn(lacc, __fmul_rn(d, d));
      }
    }
    __syncthreads();          // rv reads done above; safe to reuse
    rv[r * 33 + cg] = lacc;
    __syncthreads();
    if (t < 32 && t < nvalid){
      float s = 0.f;
      #pragma unroll
      for (int q = 0; q < 8; ++q) s = __fadd_rn(s, rv[t * 33 + q]);
      g_loss2[mn[t]] = s;
    }
  }
}

// ---------------- final loss ----------------
__global__ void vq_fin(float* __restrict__ out, int out_size){
  __shared__ double dred[256];
  const int t = threadIdx.x;
  double s = 0.0;
  for (int ii = t; ii < GRID; ii += 256) s += (double)g_partial[ii];
  for (int ii = t; ii < N_ROWS; ii += 256) s += (double)g_loss2[ii];
  dred[t] = s;
  __syncthreads();
  for (int k = 128; k > 0; k >>= 1){
    if (t < k) dred[t] += dred[t + k];
    __syncthreads();
  }
  if (t == 0 && out_size >= NZQ + N_ROWS + 1){
    float m1 = (float)(dred[0] / 33554432.0);
    float loss = __fsub_rn(m1, __fmul_rn(0.25f, m1));
    out[NZQ + N_ROWS] = loss;
  }
}

extern "C" void kernel_launch(void* const* d_in, const int* in_sizes, int n_in,
                              void* d_out, int out_size){
  const float* z   = (const float*)d_in[0];
  const float* emb = (const float*)d_in[1];
  float* out = (float*)d_out;
  (void)in_sizes; (void)n_in;

  cudaFuncSetAttribute(vq_filt, cudaFuncAttributeMaxDynamicSharedMemorySize, SM_TOTAL);
  cudaFuncSetAttribute(vq_refine, cudaFuncAttributeMaxDynamicSharedMemorySize, R_SM_TOTAL);

  zero_cnt<<<1, 1>>>();                      // launch 0
  prep_e<<<K_CODES, C_DIM>>>(emb);           // launch 1
  dummy_k<<<1, 32>>>();                      // launch 2
  vq_filt<<<GRID, 256, SM_TOTAL>>>(z, emb, out, out_size);  // launch 3 (ncu target)
  vq_refine<<<RCAP / RB_ROWS, 256, R_SM_TOTAL>>>(z, emb, out, out_size);  // launch 4
  vq_fin<<<1, 256>>>(out, out_size);         // launch 5
}

// round 17
// speedup vs baseline: 1.6000x; 1.1134x over previous
#include <cuda_runtime.h>
#include <cuda_fp16.h>
#include <cstdint>

#define N_ROWS  131072
#define C_DIM   256
#define K_CODES 1024
#define NZQ     33554432
#define HWSZ    4096
#define ROWS_CTA 64
#define GRID    (N_ROWS / ROWS_CTA)
#define RCAP    16384
#define MARGIN  1.2e-4f
#define R_ROWS  64

#define ESCALE    4096.0f          // 2^12: lift emb fp16 out of subnormal range
#define EINVSCALE 0.000244140625f  // 2^-12 (exact)

__device__ __half g_es[2u * K_CODES * C_DIM];  // 2-split of (e*2^12); plane 0 = h0 (filter uses it)
__device__ float  g_e2[K_CODES];
__device__ float  g_z2[N_ROWS];
__device__ float  g_partial[GRID];
__device__ float  g_loss2[N_ROWS];
__device__ int    g_cnt;
__device__ int    g_worklist[RCAP];

__device__ __forceinline__ uint32_t smem_u32(const void* p){
  uint32_t a;
  asm("{ .reg .u64 t; cvta.to.shared.u64 t, %1; cvt.u32.u64 %0, t; }" : "=r"(a) : "l"(p));
  return a;
}
__device__ __forceinline__ uint32_t swz(uint32_t off){ return off ^ ((off >> 3) & 0x70); }

__device__ __forceinline__ void split2(float v, uint32_t &s0, uint32_t &s1){
  __half h0 = __float2half_rn(v);
  float r  = __fsub_rn(v, __half2float(h0));
  __half h1 = __float2half_rn(r);
  s0 = (uint32_t)__half_as_ushort(h0);
  s1 = (uint32_t)__half_as_ushort(h1);
}

#define CPASYNC16(dst, src) \
  asm volatile("cp.async.cg.shared.global [%0], [%1], 16;" :: "r"(dst), "l"(src))
#define CPCOMMIT() asm volatile("cp.async.commit_group;")

#define LDSM_X4(r0,r1,r2,r3,addr) \
  asm volatile("ldmatrix.sync.aligned.m8n8.x4.shared.b16 {%0,%1,%2,%3}, [%4];" \
    : "=r"(r0), "=r"(r1), "=r"(r2), "=r"(r3) : "r"(addr))

#define MMA16816(c0,c1,c2,c3,a0,a1,a2,a3,b0,b1) \
  asm volatile("mma.sync.aligned.m16n8k16.row.col.f32.f16.f16.f32 " \
    "{%0,%1,%2,%3}, {%4,%5,%6,%7}, {%8,%9}, {%0,%1,%2,%3};" \
    : "+f"(c0), "+f"(c1), "+f"(c2), "+f"(c3) \
    : "r"(a0), "r"(a1), "r"(a2), "r"(a3), "r"(b0), "r"(b1))

#define STS128(addr, a0, a1, a2, a3) \
  asm volatile("st.shared.v4.b32 [%0], {%1,%2,%3,%4};" :: "r"(addr), "r"(a0), "r"(a1), "r"(a2), "r"(a3) : "memory")

// ---------------- prep: emb 2-split (scaled) + exact ||e||^2 ----------------
__global__ void prep_e(const float* __restrict__ emb){
  int k = blockIdx.x, c = threadIdx.x;
  float v = emb[k * C_DIM + c];
  uint32_t s0, s1;
  split2(v * ESCALE, s0, s1);
  g_es[(0u * K_CODES + k) * C_DIM + c] = __ushort_as_half((unsigned short)s0);
  g_es[(1u * K_CODES + k) * C_DIM + c] = __ushort_as_half((unsigned short)s1);
  __shared__ float red[C_DIM];
  red[c] = __fmul_rn(v, v);
  __syncthreads();
  for (int s = 128; s > 0; s >>= 1){
    if (c < s) red[c] = __fadd_rn(red[c], red[c + s]);
    __syncthreads();
  }
  if (c == 0) g_e2[k] = red[0];
}

__global__ void zero_cnt(){ g_cnt = 0; }
__global__ void dummy_k(){}

// ---------------- filter: 1-pass fp16 GEMM + top-2 + fused epilogue (R15/16, unchanged) ----------------
#define SM_A      0
#define SM_B      32768
#define OFF_E2S   65536
#define OFF_Z2S   69632
#define OFF_V1    69888
#define OFF_I1    70912
#define OFF_V2    71936
#define OFF_SIDX  72960
#define OFF_AMB   73216
#define OFF_RED   73472
#define SM_TOTAL  74496

__global__ __launch_bounds__(256, 2) void vq_filt(const float* __restrict__ z,
                                                  const float* __restrict__ emb,
                                                  float* __restrict__ out,
                                                  int out_size){
  extern __shared__ char smem[];
  const uint32_t sb = smem_u32(smem);
  float* e2s  = (float*)(smem + OFF_E2S);
  float* z2s  = (float*)(smem + OFF_Z2S);
  float* V1   = (float*)(smem + OFF_V1);
  int*   I1   = (int*)(smem + OFF_I1);
  float* V2   = (float*)(smem + OFF_V2);
  int*   sidx = (int*)(smem + OFF_SIDX);
  int*   samb = (int*)(smem + OFF_AMB);
  float* red  = (float*)(smem + OFF_RED);

  const int t = threadIdx.x, w = t >> 5, l = t & 31;
  const int wm = (w & 1) * 32;
  const int g  = w >> 1;
  const int wn = g * 32;
  const int n0 = blockIdx.x * ROWS_CTA;
  const int b  = n0 >> 12, hw0 = n0 & 4095;
  const float* zb = z + (size_t)b * (C_DIM * HWSZ) + hw0;

  auto issue = [&](int stage){
    const int nt2 = stage >> 2, kc2 = stage & 3, buf2 = stage & 1;
    #pragma unroll
    for (int i = 0; i < 4; ++i){
      int id = t + i * 256;
      int r = id >> 3, j = id & 7;
      const __half* src = g_es + (size_t)(nt2 * 128 + r) * C_DIM + kc2 * 64 + j * 8;  // plane 0
      CPASYNC16(sb + SM_B + buf2 * 16384 + swz((uint32_t)(r * 128 + j * 16)), src);
    }
    CPCOMMIT();
  };

  issue(0);
  issue(1);

  {
    const int row = t & 63, q = t >> 6;
    #pragma unroll
    for (int cg = 0; cg < 8; ++cg){
      uint32_t p0[4];
      #pragma unroll
      for (int j2 = 0; j2 < 4; ++j2){
        int c = q * 64 + cg * 8 + j2 * 2;
        uint32_t a0 = (uint32_t)__half_as_ushort(__float2half_rn(__ldg(zb + (size_t)c * HWSZ + row)));
        uint32_t b0 = (uint32_t)__half_as_ushort(__float2half_rn(__ldg(zb + (size_t)(c + 1) * HWSZ + row)));
        p0[j2] = a0 | (b0 << 16);
      }
      STS128(sb + SM_A + q * 8192 + swz((uint32_t)(row * 128 + cg * 16)),
             p0[0], p0[1], p0[2], p0[3]);
    }
  }
  for (int i = t; i < 1024; i += 256) e2s[i] = g_e2[i];
  if (t < 64){
    float acc2 = 0.f;
    #pragma unroll 8
    for (int c = 0; c < 256; ++c){
      float v = __ldg(zb + (size_t)c * HWSZ + t);
      acc2 = __fadd_rn(acc2, __fmul_rn(v, v));
    }
    z2s[t] = acc2;
    g_z2[n0 + t] = acc2;
  }
  __syncthreads();

  float acc[2][4][4];
  float rv1[4], rv2[4]; int ri1[4];
  #pragma unroll
  for (int s2 = 0; s2 < 4; ++s2){ rv1[s2] = 3.4028235e38f; rv2[s2] = 3.4028235e38f; ri1[s2] = 0; }

  const uint32_t arow = (uint32_t)(wm + (l & 7) + ((l >> 3) & 1) * 8);
  const uint32_t nrow0 = (uint32_t)(wn + ((l >> 4) << 3) + (l & 7));
  const uint32_t nrow1 = nrow0 + 16;

  for (int st = 0; st < 32; ++st){
    const int nt = st >> 2, kc = st & 3, buf = st & 1;

    if (st < 31) asm volatile("cp.async.wait_group 1;" ::: "memory");
    else         asm volatile("cp.async.wait_group 0;" ::: "memory");
    __syncthreads();

    if (kc == 0){
      #pragma unroll
      for (int ma = 0; ma < 2; ++ma)
        #pragma unroll
        for (int na = 0; na < 4; ++na)
          #pragma unroll
          for (int q = 0; q < 4; ++q) acc[ma][na][q] = 0.f;
    }

    const uint32_t Ab = sb + SM_A + (uint32_t)kc * 8192;
    const uint32_t Bb = sb + SM_B + (uint32_t)buf * 16384;

    #pragma unroll
    for (int k16 = 0; k16 < 4; ++k16){
      const uint32_t kbA = (uint32_t)(k16 * 32) + (uint32_t)((l >> 4) << 4);
      const uint32_t kbB = (uint32_t)(k16 * 32) + (uint32_t)(((l >> 3) & 1) << 4);
      uint32_t af[2][4], bf[4][2];
      #pragma unroll
      for (int ma = 0; ma < 2; ++ma)
        LDSM_X4(af[ma][0], af[ma][1], af[ma][2], af[ma][3],
                Ab + swz((arow + ma * 16) * 128 + kbA));
      LDSM_X4(bf[0][0], bf[0][1], bf[1][0], bf[1][1], Bb + swz(nrow0 * 128 + kbB));
      LDSM_X4(bf[2][0], bf[2][1], bf[3][0], bf[3][1], Bb + swz(nrow1 * 128 + kbB));
      #pragma unroll
      for (int ma = 0; ma < 2; ++ma)
        #pragma unroll
        for (int na = 0; na < 4; ++na)
          MMA16816(acc[ma][na][0], acc[ma][na][1], acc[ma][na][2], acc[ma][na][3],
                   af[ma][0], af[ma][1], af[ma][2], af[ma][3], bf[na][0], bf[na][1]);
    }
    __syncthreads();
    if (st + 2 < 32) issue(st + 2);

    if (kc == 3){
      #pragma unroll
      for (int ma = 0; ma < 2; ++ma){
        #pragma unroll
        for (int h = 0; h < 2; ++h){
          int slot = ma * 2 + h;
          int row = wm + ma * 16 + (l >> 2) + h * 8;
          float z2v = z2s[row];
          #pragma unroll
          for (int na = 0; na < 4; ++na){
            #pragma unroll
            for (int c2 = 0; c2 < 2; ++c2){
              int code = nt * 128 + wn + na * 8 + (l & 3) * 2 + c2;
              float dot = acc[ma][na][h * 2 + c2] * EINVSCALE;
              float dist = __fsub_rn(__fadd_rn(z2v, e2s[code]), __fmul_rn(2.0f, dot));
              if (dist < rv1[slot]){ rv2[slot] = rv1[slot]; rv1[slot] = dist; ri1[slot] = code; }
              else if (dist < rv2[slot]){ rv2[slot] = dist; }
            }
          }
        }
      }
    }
  }

  #pragma unroll
  for (int slot = 0; slot < 4; ++slot){
    #pragma unroll
    for (int m = 1; m <= 2; m <<= 1){
      float o1 = __shfl_xor_sync(0xffffffffu, rv1[slot], m);
      int   oi = __shfl_xor_sync(0xffffffffu, ri1[slot], m);
      float o2 = __shfl_xor_sync(0xffffffffu, rv2[slot], m);
      if (o1 < rv1[slot] || (o1 == rv1[slot] && oi < ri1[slot])){
        rv2[slot] = fminf(rv1[slot], o2); rv1[slot] = o1; ri1[slot] = oi;
      } else {
        rv2[slot] = fminf(rv2[slot], o1);
      }
    }
  }
  if ((l & 3) == 0){
    #pragma unroll
    for (int slot = 0; slot < 4; ++slot){
      int row = wm + (slot >> 1) * 16 + (l >> 2) + (slot & 1) * 8;
      V1[g * 64 + row] = rv1[slot]; I1[g * 64 + row] = ri1[slot]; V2[g * 64 + row] = rv2[slot];
    }
  }
  __syncthreads();

  if (t < 64){
    float v1 = V1[t]; int i1 = I1[t]; float v2 = V2[t];
    #pragma unroll
    for (int gg = 1; gg < 4; ++gg){
      float o1 = V1[gg * 64 + t]; int oi = I1[gg * 64 + t]; float o2 = V2[gg * 64 + t];
      if (o1 < v1 || (o1 == v1 && oi < i1)){ v2 = fminf(v1, o2); v1 = o1; i1 = oi; }
      else v2 = fminf(v2, o1);
    }
    int n = n0 + t;
    bool amb = (__fsub_rn(v2, v1) <= MARGIN);
    if (amb){
      int pos = atomicAdd(&g_cnt, 1);
      if (pos < RCAP){
        g_worklist[pos] = n;
        samb[t] = 1;
        sidx[t] = i1;
      } else {
        amb = false;
      }
    }
    if (!amb){
      samb[t] = 0;
      sidx[t] = i1;
      g_loss2[n] = 0.f;
      if (out_size >= NZQ + N_ROWS) out[NZQ + n] = (float)i1;
    }
  }
  __syncthreads();

  {
    const int i = t & 63, q = t >> 6;
    const int code = sidx[i];
    const int skip = samb[i];
    const float* erow = emb + (size_t)code * C_DIM;
    float lacc = 0.f;
    const bool wr = (out_size >= NZQ);
    if (!skip){
      #pragma unroll 4
      for (int c = q; c < 256; c += 4){
        float e  = __ldg(&erow[c]);
        size_t a = (size_t)b * (C_DIM * HWSZ) + hw0 + (size_t)c * HWSZ + i;
        float zp = z[a];
        float d  = __fsub_rn(e, zp);
        if (wr) out[a] = __fadd_rn(zp, d);
        lacc = __fadd_rn(lacc, __fmul_rn(d, d));
      }
    }
    red[t] = lacc;
    __syncthreads();
    for (int s = 128; s > 0; s >>= 1){
      if (t < s) red[t] = __fadd_rn(red[t], red[t + s]);
      __syncthreads();
    }
    if (t == 0) g_partial[blockIdx.x] = red[0];
  }
}

// ---------------- refine: R6 engine (2-split 3-pass HMMA) on worklist rows ----------------
#define RF_A      0        // [4 q][2 s][64 r][64 c] = 65536
#define RF_B      65536    // [2 buf][2 s][128 code][32 c] = 32768
#define RF_E2S    98304
#define RF_Z2S    102400
#define RF_SMINV  102656
#define RF_SMINI  103680
#define RF_SIDX   104704
#define RF_RED    104960
#define RF_MN     105984
#define RF_MB     106240
#define RF_MHW    106496
#define RF_TOTAL  106752

__global__ __launch_bounds__(256, 2) void vq_refine(const float* __restrict__ z,
                                                    const float* __restrict__ emb,
                                                    float* __restrict__ out,
                                                    int out_size){
  extern __shared__ char smem[];
  const uint32_t sb = smem_u32(smem);
  float* e2s   = (float*)(smem + RF_E2S);
  float* z2s   = (float*)(smem + RF_Z2S);
  float* sminv = (float*)(smem + RF_SMINV);
  int*   smini = (int*)(smem + RF_SMINI);
  int*   sidx  = (int*)(smem + RF_SIDX);
  float* red   = (float*)(smem + RF_RED);
  int*   mn    = (int*)(smem + RF_MN);
  int*   mb    = (int*)(smem + RF_MB);
  int*   mhw   = (int*)(smem + RF_MHW);

  int cnt = g_cnt; if (cnt > RCAP) cnt = RCAP;
  const int base = blockIdx.x * R_ROWS;
  if (base >= cnt) return;
  const int nv = min(R_ROWS, cnt - base);

  const int t = threadIdx.x, w = t >> 5, l = t & 31;
  const int wm = (w & 1) * 32;
  const int g  = w >> 1;
  const int wn = g * 32;

  auto issue = [&](int stage){
    const int nt2 = stage >> 3, kc2 = (stage >> 1) & 3, ch2 = stage & 1, buf2 = stage & 1;
    #pragma unroll
    for (int i = 0; i < 4; ++i){
      int id = t + i * 256;
      int s = id >> 9, rem = id & 511;
      int r = rem >> 2, cch = rem & 3;
      const __half* src = g_es + ((size_t)s * K_CODES + nt2 * 128 + r) * C_DIM + kc2 * 64 + ch2 * 32 + cch * 8;
      CPASYNC16(sb + RF_B + buf2 * 16384 + s * 8192 + swz((uint32_t)(r * 64 + cch * 16)), src);
    }
    CPCOMMIT();
  };

  if (t < 64){
    int n = g_worklist[base + ((t < nv) ? t : 0)];
    mn[t] = n; mb[t] = n >> 12; mhw[t] = n & 4095;
    z2s[t] = g_z2[n];
  }
  issue(0);
  issue(1);
  __syncthreads();   // meta visible before phase-1 row-base reads

  // ---- phase 1: gather + 2-split -> A smem ----
  {
    const int row = t & 63, q = t >> 6;
    const size_t zb = (size_t)(mb[row] * 256) * HWSZ + (size_t)mhw[row];
    #pragma unroll
    for (int cg = 0; cg < 8; ++cg){
      uint32_t p0[4], p1[4];
      #pragma unroll
      for (int j2 = 0; j2 < 4; ++j2){
        int c = q * 64 + cg * 8 + j2 * 2;
        float va = __ldg(z + zb + (size_t)c * HWSZ);
        float vb = __ldg(z + zb + (size_t)(c + 1) * HWSZ);
        uint32_t a0, a1, b0, b1;
        split2(va, a0, a1); split2(vb, b0, b1);
        p0[j2] = a0 | (b0 << 16);
        p1[j2] = a1 | (b1 << 16);
      }
      uint32_t ad = swz((uint32_t)(row * 128 + cg * 16));
      STS128(sb + RF_A + q * 16384 + ad,        p0[0], p0[1], p0[2], p0[3]);
      STS128(sb + RF_A + q * 16384 + 8192 + ad, p1[0], p1[1], p1[2], p1[3]);
    }
  }
  for (int i = t; i < 1024; i += 256) e2s[i] = g_e2[i];
  sminv[t] = 3.4028235e38f; smini[t] = 0;
  __syncthreads();

  float acc[2][4][4];
  const int pa[3] = {0,0,1}, pb[3] = {0,1,0};

  for (int st = 0; st < 64; ++st){
    const int nt = st >> 3, kc = (st >> 1) & 3, ch = st & 1, buf = st & 1;

    if (st < 63) asm volatile("cp.async.wait_group 1;" ::: "memory");
    else         asm volatile("cp.async.wait_group 0;" ::: "memory");
    __syncthreads();

    if ((st & 7) == 0){
      #pragma unroll
      for (int ma = 0; ma < 2; ++ma)
        #pragma unroll
        for (int na = 0; na < 4; ++na)
          #pragma unroll
          for (int q = 0; q < 4; ++q) acc[ma][na][q] = 0.f;
    }

    const uint32_t Ab = sb + RF_A + (uint32_t)kc * 16384;
    const uint32_t Bb = sb + RF_B + (uint32_t)buf * 16384;
    #pragma unroll
    for (int k16l = 0; k16l < 2; ++k16l){
      const uint32_t kbA = (uint32_t)(ch * 64 + k16l * 32);
      const uint32_t kbB = (uint32_t)(k16l * 32);
      uint32_t af[2][2][4], bf[2][4][2];
      #pragma unroll
      for (int s = 0; s < 2; ++s){
        #pragma unroll
        for (int ma = 0; ma < 2; ++ma){
          uint32_t row = (uint32_t)(wm + ma * 16 + (l & 7) + ((l >> 3) & 1) * 8);
          uint32_t ad = Ab + s * 8192 + swz(row * 128 + kbA + ((l >> 4) << 4));
          LDSM_X4(af[s][ma][0], af[s][ma][1], af[s][ma][2], af[s][ma][3], ad);
        }
        #pragma unroll
        for (int p = 0; p < 2; ++p){
          uint32_t nrow = (uint32_t)(wn + p * 16 + ((l >> 4) << 3) + (l & 7));
          uint32_t bd = Bb + s * 8192 + swz(nrow * 64 + kbB + (((l >> 3) & 1) << 4));
          LDSM_X4(bf[s][2*p][0], bf[s][2*p][1], bf[s][2*p+1][0], bf[s][2*p+1][1], bd);
        }
      }
      #pragma unroll
      for (int p = 0; p < 3; ++p){
        const int sa = pa[p], sbp = pb[p];
        #pragma unroll
        for (int ma = 0; ma < 2; ++ma)
          #pragma unroll
          for (int na = 0; na < 4; ++na)
            MMA16816(acc[ma][na][0], acc[ma][na][1], acc[ma][na][2], acc[ma][na][3],
                     af[sa][ma][0], af[sa][ma][1], af[sa][ma][2], af[sa][ma][3],
                     bf[sbp][na][0], bf[sbp][na][1]);
      }
    }
    __syncthreads();
    if (st + 2 < 64) issue(st + 2);

    if ((st & 7) == 7){
      #pragma unroll
      for (int ma = 0; ma < 2; ++ma){
        #pragma unroll
        for (int h = 0; h < 2; ++h){
          int row = wm + ma * 16 + (l >> 2) + h * 8;
          float z2v = z2s[row];
          float bv = 3.4028235e38f; int bi = 0;
          #pragma unroll
          for (int na = 0; na < 4; ++na){
            #pragma unroll
            for (int c2 = 0; c2 < 2; ++c2){
              int code = nt * 128 + wn + na * 8 + (l & 3) * 2 + c2;
              float dot = acc[ma][na][h * 2 + c2] * EINVSCALE;
              float sd = __fadd_rn(z2v, e2s[code]);
              float dist = __fsub_rn(sd, __fmul_rn(2.0f, dot));
              if (dist < bv){ bv = dist; bi = code; }
            }
          }
          #pragma unroll
          for (int m = 1; m <= 2; m <<= 1){
            float ov = __shfl_xor_sync(0xffffffffu, bv, m);
            int   oi = __shfl_xor_sync(0xffffffffu, bi, m);
            if (ov < bv || (ov == bv && oi < bi)){ bv = ov; bi = oi; }
          }
          if ((l & 3) == 0){
            int idx = g * 64 + row;
            if (bv < sminv[idx] || (bv == sminv[idx] && bi < smini[idx])){
              sminv[idx] = bv; smini[idx] = bi;
            }
          }
        }
      }
    }
  }
  __syncthreads();

  if (t < 64){
    float bv = sminv[t]; int bi = smini[t];
    #pragma unroll
    for (int gg = 1; gg < 4; ++gg){
      float ov = sminv[gg * 64 + t]; int oi = smini[gg * 64 + t];
      if (ov < bv || (ov == bv && oi < bi)){ bv = ov; bi = oi; }
    }
    sidx[t] = bi;
    if (out_size >= NZQ + N_ROWS) out[NZQ + mn[t]] = (float)bi;
  }
  __syncthreads();

  // ---- epilogue: gather zq, straight-through, per-row loss ----
  {
    const int i = t & 63, q = t >> 6;
    const int code = sidx[i];
    const size_t zb2 = (size_t)(mb[i] * 256) * HWSZ + (size_t)mhw[i];
    const float* erow = emb + (size_t)code * C_DIM;
    float lacc = 0.f;
    const bool wr = (out_size >= NZQ);
    #pragma unroll 4
    for (int c = q; c < 256; c += 4){
      float e  = __ldg(&erow[c]);
      size_t a = zb2 + (size_t)c * HWSZ;
      float zp = __ldg(z + a);
      float d  = __fsub_rn(e, zp);
      if (wr) out[a] = __fadd_rn(zp, d);
      lacc = __fadd_rn(lacc, __fmul_rn(d, d));
    }
    red[q * 64 + i] = lacc;
    __syncthreads();
    if (t < 64){
      float s = red[t];
      s = __fadd_rn(s, red[64 + t]);
      s = __fadd_rn(s, red[128 + t]);
      s = __fadd_rn(s, red[192 + t]);
      g_loss2[mn[t]] = s;
    }
  }
}

// ---------------- final loss ----------------
__global__ void vq_fin(float* __restrict__ out, int out_size){
  __shared__ double dred[256];
  const int t = threadIdx.x;
  double s = 0.0;
  for (int ii = t; ii < GRID; ii += 256) s += (double)g_partial[ii];
  for (int ii = t; ii < N_ROWS; ii += 256) s += (double)g_loss2[ii];
  dred[t] = s;
  __syncthreads();
  for (int k = 128; k > 0; k >>= 1){
    if (t < k) dred[t] += dred[t + k];
    __syncthreads();
  }
  if (t == 0 && out_size >= NZQ + N_ROWS + 1){
    float m1 = (float)(dred[0] / 33554432.0);
    float loss = __fsub_rn(m1, __fmul_rn(0.25f, m1));
    out[NZQ + N_ROWS] = loss;
  }
}

extern "C" void kernel_launch(void* const* d_in, const int* in_sizes, int n_in,
                              void* d_out, int out_size){
  const float* z   = (const float*)d_in[0];
  const float* emb = (const float*)d_in[1];
  float* out = (float*)d_out;
  (void)in_sizes; (void)n_in;

  cudaFuncSetAttribute(vq_filt, cudaFuncAttributeMaxDynamicSharedMemorySize, SM_TOTAL);
  cudaFuncSetAttribute(vq_refine, cudaFuncAttributeMaxDynamicSharedMemorySize, RF_TOTAL);

  zero_cnt<<<1, 1>>>();                      // launch 0
  prep_e<<<K_CODES, C_DIM>>>(emb);           // launch 1
  dummy_k<<<1, 32>>>();                      // launch 2
  vq_filt<<<GRID, 256, SM_TOTAL>>>(z, emb, out, out_size);  // launch 3 (ncu target)
  vq_refine<<<RCAP / R_ROWS, 256, RF_TOTAL>>>(z, emb, out, out_size);  // launch 4
  vq_fin<<<1, 256>>>(out, out_size);         // launch 5
}